// round 10
// baseline (speedup 1.0000x reference)
#include <cuda_runtime.h>

typedef unsigned int u32;
typedef unsigned long long u64;

namespace {
constexpr int B_     = 2;
constexpr int N_     = 8192;
constexpr int KNN    = 10;
constexpr int KP1    = 11;
constexpr int SPLIT  = 8;
constexpr int QPB    = 64;
constexpr int THREADS = QPB * SPLIT;          // 512
constexpr int SUBLEN  = N_ / SPLIT;           // 1024
constexpr int GROUP   = 16;
constexpr int NGROUPS = SUBLEN / GROUP;       // 64
constexpr int WARM    = 6;                    // 96 exact warm-up candidates
constexpr int BPB     = N_ / QPB;             // 128 blocks per batch
constexpr int NBLOCKS = B_ * BPB;             // 256  -> 2 blocks/SM (96KB smem each)
constexpr int GTOT    = NBLOCKS * THREADS;    // 131072
constexpr int LOGCAP  = 160;
constexpr u64 STRIDEB = (u64)GTOT * 8ull;     // 1MB = 2^20 (coalesced log stride)
constexpr int NPAIR   = N_ / 2;               // 4096
constexpr int SMEM_BYTES = 3 * NPAIR * 8;     // 96KB: xp/yp/zp pair arrays
}

__device__ float g_partials[NBLOCKS];
__device__ u64   g_log[(size_t)LOGCAP * GTOT];   // 160MB static scratch (legal)

__device__ __forceinline__ u64 pk2(float a, float b) {
    u64 r; asm("mov.b64 %0, {%1, %2};" : "=l"(r) : "f"(a), "f"(b)); return r;
}
__device__ __forceinline__ u64 fma2(u64 a, u64 b, u64 c) {
    u64 d; asm("fma.rn.f32x2 %0, %1, %2, %3;" : "=l"(d) : "l"(a), "l"(b), "l"(c)); return d;
}
__device__ __forceinline__ void unpk(u64 v, u32& lo, u32& hi) {
    asm("mov.b64 {%0, %1}, %2;" : "=r"(lo), "=r"(hi) : "l"(v));
}
__device__ __forceinline__ u32 umn(u32 a, u32 b) { return a < b ? a : b; }
__device__ __forceinline__ float uasf(u32 x) { return __uint_as_float(x); }
__device__ __forceinline__ u32  fasu(float x) { return __float_as_uint(x); }

// Float sorted-insert chain: 2 FMNMX per level (fma pipe -> balances alu pipe).
// Valid because all keys are strictly positive floats (uint order == float order).
__device__ __forceinline__ void ins11f(float c, float (&kd)[KP1]) {
#pragma unroll
    for (int t = 0; t < KP1; ++t) {
        const float lo = fminf(c, kd[t]);
        const float hi = fmaxf(c, kd[t]);
        kd[t] = lo; c = hi;
    }
}
// u32 variant for recovery/merge (off the hot path).
__device__ __forceinline__ void ins11u(u32 c, u32 (&kd)[KP1]) {
#pragma unroll
    for (int t = 0; t < KP1; ++t) {
        const u32 lo = umn(c, kd[t]);
        const u32 hi = (c > kd[t]) ? c : kd[t];
        kd[t] = lo; c = hi;
    }
}

// Predicated conditional log: if key < thr (u32 compare == float compare, both
// positive), store {key, jg} and bump addr. No BSSY/BSYNC.
__device__ __forceinline__ void logcand(u64& addr, u32 key, u32 thr, u32 jgu) {
    asm volatile(
        "{\n\t.reg .pred p;\n\t"
        "setp.lt.u32 p, %1, %2;\n\t"
        "@p st.global.v2.b32 [%0], {%1, %3};\n\t"
        "@p add.u64 %0, %0, %4;\n\t}"
        : "+l"(addr)
        : "r"(key), "r"(thr), "r"(jgu), "l"(STRIDEB)
        : "memory");
}

__global__ __launch_bounds__(THREADS, 2)
void knn_lap_loss_kernel(const float* __restrict__ p1, const float* __restrict__ p2) {
    extern __shared__ u64 sm[];
    u64* xp = sm;
    u64* yp = sm + NPAIR;
    u64* zp = sm + 2 * NPAIR;

    const int tid   = threadIdx.x;
    const int gtid  = blockIdx.x * THREADS + tid;
    const int b     = blockIdx.x / BPB;
    const int qbase = (blockIdx.x % BPB) * QPB;
    const float* __restrict__ p1b = p1 + (size_t)b * N_ * 3;
    const float* __restrict__ p2b = p2 + (size_t)b * N_ * 3;

    // ---- Phase 1: stage point1 as pair-SoA u64 arrays (12B/point => 96KB) ----
    for (int p = tid; p < NPAIR; p += THREADS) {
        const int a = 2 * p;
        xp[p] = pk2(p1b[a*3+0], p1b[a*3+3]);
        yp[p] = pk2(p1b[a*3+1], p1b[a*3+4]);
        zp[p] = pk2(p1b[a*3+2], p1b[a*3+5]);
    }
    __syncthreads();

    // ---- Query constants. key = (c-q)^2 + 1 > 0 strictly. ----
    const int q   = tid & (QPB - 1);
    const int sub = tid >> 6;           // 0..7 (constant within a warp)
    const int qi  = qbase + q;
    const float qx = p1b[qi*3+0], qy = p1b[qi*3+1], qz = p1b[qi*3+2];
    const u64 nqx2 = pk2(-qx, -qx);
    const u64 nqy2 = pk2(-qy, -qy);
    const u64 nqz2 = pk2(-qz, -qz);
    const u64 one2 = pk2(1.0f, 1.0f);

    float kd[KP1];
#pragma unroll
    for (int t = 0; t < KP1; ++t) kd[t] = 3.0e38f;

    u64 addr        = (u64)(g_log + gtid);
    const u64 base  = addr;
    const u64 limit = base + (u64)(LOGCAP - GROUP) * STRIDEB;

    const int jbeg = sub * SUBLEN;

    // ---- Phase 2a: exact warm-up (first 11 candidates always log => cnt>=11) ----
    for (int g = 0; g < WARM; ++g) {
        const int jg = jbeg + g * GROUP;
        const int pb = jg >> 1;
        const u32 jgu = (u32)jg;
#pragma unroll
        for (int pp = 0; pp < GROUP / 2; ++pp) {
            const u64 dx = fma2(xp[pb+pp], one2, nqx2);
            const u64 dy = fma2(yp[pb+pp], one2, nqy2);
            const u64 dz = fma2(zp[pb+pp], one2, nqz2);
            u64 acc = fma2(dx, dx, one2);
            acc = fma2(dy, dy, acc);
            acc = fma2(dz, dz, acc);
            u32 lo, hi; unpk(acc, lo, hi);
            const u32 klo = (lo & 0xFFFFFFF0u) | (u32)(2*pp);
            const u32 khi = (hi & 0xFFFFFFF0u) | (u32)(2*pp+1);
            u32 thr = (addr <= limit) ? fasu(kd[KP1-1]) : 0u;
            logcand(addr, klo, thr, jgu);
            ins11f(uasf(klo), kd);
            thr = (addr <= limit) ? fasu(kd[KP1-1]) : 0u;
            logcand(addr, khi, thr, jgu);
            ins11f(uasf(khi), kd);
        }
    }

    // ---- Phase 2b: streaming main scan: log + running group-min, 1 chain/group ----
    for (int g = WARM; g < NGROUPS; ++g) {
        const int jg = jbeg + g * GROUP;
        const int pb = jg >> 1;
        const u32 jgu = (u32)jg;
        const u32 thr = (addr <= limit) ? fasu(kd[KP1-1]) : 0u;
        float m = 3.0e38f;
#pragma unroll
        for (int pp = 0; pp < GROUP / 2; ++pp) {
            const u64 dx = fma2(xp[pb+pp], one2, nqx2);
            const u64 dy = fma2(yp[pb+pp], one2, nqy2);
            const u64 dz = fma2(zp[pb+pp], one2, nqz2);
            u64 acc = fma2(dx, dx, one2);
            acc = fma2(dy, dy, acc);
            acc = fma2(dz, dz, acc);
            u32 lo, hi; unpk(acc, lo, hi);
            const u32 klo = (lo & 0xFFFFFFF0u) | (u32)(2*pp);
            const u32 khi = (hi & 0xFFFFFFF0u) | (u32)(2*pp+1);
            logcand(addr, klo, thr, jgu);
            logcand(addr, khi, thr, jgu);
            m = fminf(m, fminf(uasf(klo), uasf(khi)));
        }
        ins11f(m, kd);   // threshold-oracle update (upper bound of true 11th -> safe)
    }

    // ---- Phase 3: exact recovery from this thread's log ----
    const u32 cnt = (u32)((addr - base) >> 20);   // STRIDEB = 2^20
    u32 rc[KP1];
#pragma unroll
    for (int t = 0; t < KP1; ++t) rc[t] = 0xFFFFFFFFu;
    for (u32 i = 0; i < cnt; ++i) {
        const u64 e = *reinterpret_cast<const u64*>(base + (u64)i * STRIDEB);
        ins11u(((u32)e & 0xFFFFFF00u) | i, rc);
    }

    __syncthreads();   // done reading staged points; smem reused below

    // ---- Phase 4: decode indices, dump sorted lists to smem ----
    u32* sval = reinterpret_cast<u32*>(sm);
    u32* sidx = sval + THREADS * KP1;
    {
        const int dbase = (q * SPLIT + sub) * KP1;
#pragma unroll
        for (int r = 0; r < KP1; ++r) {
            const u32 pos = rc[r] & 0xFFu;   // cnt >= 11 guaranteed -> pos valid
            const u64 e = *reinterpret_cast<const u64*>(base + (u64)pos * STRIDEB);
            const u32 j = (u32)(e >> 32) + ((u32)e & 15u);
            sval[dbase + r] = rc[r];
            sidx[dbase + r] = j;
        }
    }
    __syncthreads();

    // ---- Phase 5: q-threads select top-11 of the 8x11 union via tagged chain ----
    float acc = 0.0f;
    if (tid < QPB) {
        u32 top[KP1];
#pragma unroll
        for (int t = 0; t < KP1; ++t) top[t] = 0xFFFFFFFFu;
#pragma unroll
        for (int l = 0; l < SPLIT; ++l) {
            const u32* vl = sval + (tid * SPLIT + l) * KP1;
#pragma unroll
            for (int r = 0; r < KP1; ++r)
                ins11u((vl[r] & 0xFFFFFF00u) | ((u32)l << 4) | (u32)r, top);
        }
        // top[0] is self -> neighbors are top[1..10]
        float sx = 0.0f, sy = 0.0f, sz = 0.0f;
#pragma unroll
        for (int r = 1; r < KP1; ++r) {
            const u32 t = top[r];
            const int bi = (int)sidx[(tid * SPLIT + (int)((t >> 4) & 7u)) * KP1 + (int)(t & 15u)];
            sx += p1b[bi*3+0] - p2b[bi*3+0];
            sy += p1b[bi*3+1] - p2b[bi*3+1];
            sz += p1b[bi*3+2] - p2b[bi*3+2];
        }
        const int qj = qbase + tid;
        const float dqx = p1b[qj*3+0] - p2b[qj*3+0];
        const float dqy = p1b[qj*3+1] - p2b[qj*3+1];
        const float dqz = p1b[qj*3+2] - p2b[qj*3+2];
        const float inv_k = 1.0f / (float)KNN;
        acc = fabsf(fmaf(sx, inv_k, -dqx))
            + fabsf(fmaf(sy, inv_k, -dqy))
            + fabsf(fmaf(sz, inv_k, -dqz));
    }

    // ---- Phase 6: deterministic block reduction ----
    float* red = reinterpret_cast<float*>(sval + 2 * THREADS * KP1);
    red[tid] = acc;
    __syncthreads();
#pragma unroll
    for (int s = THREADS / 2; s > 0; s >>= 1) {
        if (tid < s) red[tid] += red[tid + s];
        __syncthreads();
    }
    if (tid == 0) g_partials[blockIdx.x] = red[0];
}

__global__ void final_reduce_kernel(float* __restrict__ out) {
    __shared__ float s[NBLOCKS];
    const int t = threadIdx.x;
    s[t] = g_partials[t];
    __syncthreads();
#pragma unroll
    for (int st = NBLOCKS / 2; st > 0; st >>= 1) {
        if (t < st) s[t] += s[t + st];
        __syncthreads();
    }
    if (t == 0) out[0] = s[0] * (1.0f / (float)(B_ * N_ * 3));
}

extern "C" void kernel_launch(void* const* d_in, const int* in_sizes, int n_in,
                              void* d_out, int out_size) {
    const float* p1 = (const float*)d_in[0];
    const float* p2 = (const float*)d_in[1];
    (void)in_sizes; (void)n_in; (void)out_size;

    cudaFuncSetAttribute(knn_lap_loss_kernel,
                         cudaFuncAttributeMaxDynamicSharedMemorySize, SMEM_BYTES);
    knn_lap_loss_kernel<<<NBLOCKS, THREADS, SMEM_BYTES>>>(p1, p2);
    final_reduce_kernel<<<1, NBLOCKS>>>((float*)d_out);
}

// round 11
// speedup vs baseline: 1.2897x; 1.2897x over previous
#include <cuda_runtime.h>

typedef unsigned int u32;
typedef unsigned long long u64;

namespace {
constexpr int B_     = 2;
constexpr int N_     = 8192;
constexpr int KNN    = 10;
constexpr int KP1    = 11;
constexpr int SPLIT  = 4;
constexpr int QPB    = 128;
constexpr int THREADS = QPB * SPLIT;          // 512
constexpr int SUBLEN  = N_ / SPLIT;           // 2048
constexpr int GROUP   = 16;                   // candidates per group (8 pairs)
constexpr int NGROUPS = SUBLEN / GROUP;       // 128
constexpr int WARM    = 6;                    // exact warm-up groups (96 candidates)
constexpr int BPB     = N_ / QPB;             // 64
constexpr int NBLOCKS = B_ * BPB;             // 128 -> 1 block/SM
constexpr int GTOT    = NBLOCKS * THREADS;    // 65536
constexpr int LOGCAP  = 160;
constexpr u64 STRIDEB = (u64)GTOT * 16ull;    // 1MB = 2^20 (16B pair entries)
constexpr int SMEM_BYTES = N_ * 16;           // 128KB point staging
}

__device__ float g_partials[NBLOCKS];
__device__ uint4 g_log[(size_t)LOGCAP * GTOT];   // 160MB static scratch (legal)

__device__ __forceinline__ u64 pk2(float a, float b) {
    u64 r; asm("mov.b64 %0, {%1, %2};" : "=l"(r) : "f"(a), "f"(b)); return r;
}
__device__ __forceinline__ u64 fma2(u64 a, u64 b, u64 c) {
    u64 d; asm("fma.rn.f32x2 %0, %1, %2, %3;" : "=l"(d) : "l"(a), "l"(b), "l"(c)); return d;
}
__device__ __forceinline__ u64 add2(u64 a, u64 b) {
    u64 d; asm("add.rn.f32x2 %0, %1, %2;" : "=l"(d) : "l"(a), "l"(b)); return d;
}
__device__ __forceinline__ void unpk(u64 v, u32& lo, u32& hi) {
    asm("mov.b64 {%0, %1}, %2;" : "=r"(lo), "=r"(hi) : "l"(v));
}
__device__ __forceinline__ u32 umn(u32 a, u32 b) { return a < b ? a : b; }
__device__ __forceinline__ float uasf(u32 x) { return __uint_as_float(x); }

// Branchless float sorted-insert (keys strictly positive -> total order fine).
__device__ __forceinline__ void ins11f(float c, float (&kd)[KP1]) {
#pragma unroll
    for (int t = 0; t < KP1; ++t) {
        const float lo = fminf(c, kd[t]);
        const float hi = fmaxf(c, kd[t]);
        kd[t] = lo; c = hi;
    }
}
// u32 variant for recovery/merge (positive-float bit patterns + tags).
__device__ __forceinline__ void ins11u(u32 c, u32 (&kd)[KP1]) {
#pragma unroll
    for (int t = 0; t < KP1; ++t) {
        const u32 lo = umn(c, kd[t]);
        const u32 hi = (c > kd[t]) ? c : kd[t];
        kd[t] = lo; c = hi;
    }
}

// Predicated PAIR log: if pm < thr, store {klo, khi, jabs, jabs}, bump addr.
// One SETP + one STG.128 + one u64 add per PAIR. No BSSY/BSYNC.
__device__ __forceinline__ void logpair(u64& addr, float pm, float thr,
                                        u32 klo, u32 khi, u32 jabs) {
    asm volatile(
        "{\n\t.reg .pred p;\n\t"
        "setp.lt.f32 p, %1, %2;\n\t"
        "@p st.global.v4.b32 [%0], {%3, %4, %5, %5};\n\t"
        "@p add.u64 %0, %0, %6;\n\t}"
        : "+l"(addr)
        : "f"(pm), "f"(thr), "r"(klo), "r"(khi), "r"(jabs), "l"(STRIDEB)
        : "memory");
}

__global__ __launch_bounds__(THREADS, 1)
void knn_lap_loss_kernel(const float* __restrict__ p1, const float* __restrict__ p2) {
    extern __shared__ unsigned char smem_raw[];
    float4* buf = reinterpret_cast<float4*>(smem_raw);

    const int tid   = threadIdx.x;
    const int gtid  = blockIdx.x * THREADS + tid;
    const int b     = blockIdx.x / BPB;
    const int qbase = (blockIdx.x % BPB) * QPB;
    const float* __restrict__ p1b = p1 + (size_t)b * N_ * 3;
    const float* __restrict__ p2b = p2 + (size_t)b * N_ * 3;

    // ---- Phase 1: stage pairs: buf[2p]={x0,x1,y0,y1}, buf[2p+1]={z0,z1,w0,w1} ----
    for (int p = tid; p < N_ / 2; p += THREADS) {
        const int a = 2 * p, c = 2 * p + 1;
        float xa = p1b[a*3+0], ya = p1b[a*3+1], za = p1b[a*3+2];
        float xb = p1b[c*3+0], yb = p1b[c*3+1], zb = p1b[c*3+2];
        float wa = fmaf(xa, xa, fmaf(ya, ya, za * za));
        float wb = fmaf(xb, xb, fmaf(yb, yb, zb * zb));
        buf[2*p]   = make_float4(xa, xb, ya, yb);
        buf[2*p+1] = make_float4(za, zb, wa, wb);
    }
    __syncthreads();

    // ---- Query constants. key = |c|^2 - 2 q.c + |q|^2 + 1 = dist^2+1 > 0. ----
    const int q   = tid & (QPB - 1);
    const int sub = tid >> 7;           // 0..3 (constant within warp)
    const int qi  = qbase + q;
    float qx, qy, qz, qw;
    {
        const int p = qi >> 1, h = qi & 1;
        const float4 A = buf[2*p], C = buf[2*p+1];
        qx = h ? A.y : A.x;  qy = h ? A.w : A.z;
        qz = h ? C.y : C.x;  qw = h ? C.w : C.z;
    }
    const u64 m2x2 = pk2(-2.0f*qx, -2.0f*qx);
    const u64 m2y2 = pk2(-2.0f*qy, -2.0f*qy);
    const u64 m2z2 = pk2(-2.0f*qz, -2.0f*qz);
    const float qb = qw + 1.0f;
    const u64 qb2  = pk2(qb, qb);

    float kd[KP1];
#pragma unroll
    for (int t = 0; t < KP1; ++t) kd[t] = 3.0e38f;

    u64 addr        = (u64)(g_log + gtid);
    const u64 base  = addr;
    const u64 limit = base + (u64)(LOGCAP - GROUP) * STRIDEB;

    const int jbeg = sub * SUBLEN;

    // ---- Phase 2a: exact warm-up. kd starts INF -> first 6 pairs (12 keys) always
    // log => recovery sees >= 11 valid keys, guaranteed. ----
    for (int g = 0; g < WARM; ++g) {
        const int jg = jbeg + g * GROUP;
        const int pb = jg >> 1;
#pragma unroll
        for (int pp = 0; pp < GROUP / 2; ++pp) {
            const float4 A = buf[2*(pb+pp)], C = buf[2*(pb+pp)+1];
            u64 acc = add2(pk2(C.z, C.w), qb2);
            acc = fma2(pk2(A.x, A.y), m2x2, acc);
            acc = fma2(pk2(A.z, A.w), m2y2, acc);
            acc = fma2(pk2(C.x, C.y), m2z2, acc);
            u32 klo, khi; unpk(acc, klo, khi);
            const float pm = fminf(uasf(klo), uasf(khi));
            const float thr = (addr <= limit) ? kd[KP1-1] : 0.0f;
            logpair(addr, pm, thr, klo, khi, (u32)(jg + 2*pp));
            ins11f(uasf(klo), kd);
            ins11f(uasf(khi), kd);
        }
    }

    // ---- Phase 2b: main scan. Per pair: 4 wide-FMA, 1 FMNMX, 1 predicated
    // STG.128 log. Per group: 7-op min-tree + one chain insert. ----
    for (int g = WARM; g < NGROUPS; ++g) {
        const int jg = jbeg + g * GROUP;
        const int pb = jg >> 1;
        const float thr = (addr <= limit) ? kd[KP1-1] : 0.0f;
        float pm[GROUP / 2];
#pragma unroll
        for (int pp = 0; pp < GROUP / 2; ++pp) {
            const float4 A = buf[2*(pb+pp)], C = buf[2*(pb+pp)+1];
            u64 acc = add2(pk2(C.z, C.w), qb2);
            acc = fma2(pk2(A.x, A.y), m2x2, acc);
            acc = fma2(pk2(A.z, A.w), m2y2, acc);
            acc = fma2(pk2(C.x, C.y), m2z2, acc);
            u32 klo, khi; unpk(acc, klo, khi);
            pm[pp] = fminf(uasf(klo), uasf(khi));
            logpair(addr, pm[pp], thr, klo, khi, (u32)(jg + 2*pp));
        }
        // min-tree (7 FMNMX) + threshold-oracle update (upper bound of true 11th -> safe)
        const float m0 = fminf(fminf(pm[0], pm[1]), fminf(pm[2], pm[3]));
        const float m1 = fminf(fminf(pm[4], pm[5]), fminf(pm[6], pm[7]));
        ins11f(fminf(m0, m1), kd);
    }

    // ---- Phase 3: exact recovery. Tag = (slot<<1)|half in 9 masked key bits. ----
    const u32 cnt = (u32)((addr - base) >> 20);   // STRIDEB = 2^20
    u32 rc[KP1];
#pragma unroll
    for (int t = 0; t < KP1; ++t) rc[t] = 0xFFFFFFFFu;
    for (u32 i = 0; i < cnt; ++i) {
        const uint4 e = *reinterpret_cast<const uint4*>(base + (u64)i * STRIDEB);
        ins11u((e.x & 0xFFFFFE00u) | (i << 1) | 0u, rc);
        ins11u((e.y & 0xFFFFFE00u) | (i << 1) | 1u, rc);
    }

    __syncthreads();   // done reading staged points; smem reused below

    // ---- Phase 4: decode indices, dump sorted lists to smem ----
    u32* sval = reinterpret_cast<u32*>(smem_raw);
    u32* sidx = sval + THREADS * KP1;
    {
        const int dbase = (q * SPLIT + sub) * KP1;
#pragma unroll
        for (int r = 0; r < KP1; ++r) {
            const u32 slot = (rc[r] >> 1) & 0xFFu;   // cnt >= 6 entries guaranteed
            const u32 h    = rc[r] & 1u;
            const uint4 e  = *reinterpret_cast<const uint4*>(base + (u64)slot * STRIDEB);
            sval[dbase + r] = rc[r];
            sidx[dbase + r] = e.z + h;
        }
    }
    __syncthreads();

    // ---- Phase 5: sub==0 threads 4-way merge + gather + per-query L1 ----
    float acc = 0.0f;
    if (sub == 0) {
        const u32* v0 = sval + (q * SPLIT + 0) * KP1;
        const u32* v1 = sval + (q * SPLIT + 1) * KP1;
        const u32* v2 = sval + (q * SPLIT + 2) * KP1;
        const u32* v3 = sval + (q * SPLIT + 3) * KP1;
        const u32* i0 = sidx + (q * SPLIT + 0) * KP1;
        const u32* i1 = sidx + (q * SPLIT + 1) * KP1;
        const u32* i2 = sidx + (q * SPLIT + 2) * KP1;
        const u32* i3 = sidx + (q * SPLIT + 3) * KP1;

        int c0 = 0, c1 = 0, c2 = 0, c3 = 0;
        u32 nidx[KP1];
#pragma unroll
        for (int r = 0; r < KP1; ++r) {
            const u32 h0 = v0[c0], h1 = v1[c1], h2 = v2[c2], h3 = v3[c3];
            const u32 m = umn(umn(h0, h1), umn(h2, h3));
            u32 bi;
            if (m == h0)      { bi = i0[c0]; ++c0; }
            else if (m == h1) { bi = i1[c1]; ++c1; }
            else if (m == h2) { bi = i2[c2]; ++c2; }
            else              { bi = i3[c3]; ++c3; }
            nidx[r] = bi;
        }

        // nidx[0] is self (key = 1.0, global min) -> neighbors are nidx[1..10]
        float sx = 0.0f, sy = 0.0f, sz = 0.0f;
#pragma unroll
        for (int r = 1; r < KP1; ++r) {
            const int bi = (int)nidx[r];
            sx += p1b[bi*3+0] - p2b[bi*3+0];
            sy += p1b[bi*3+1] - p2b[bi*3+1];
            sz += p1b[bi*3+2] - p2b[bi*3+2];
        }
        const float dqx = p1b[qi*3+0] - p2b[qi*3+0];
        const float dqy = p1b[qi*3+1] - p2b[qi*3+1];
        const float dqz = p1b[qi*3+2] - p2b[qi*3+2];
        const float inv_k = 1.0f / (float)KNN;
        acc = fabsf(fmaf(sx, inv_k, -dqx))
            + fabsf(fmaf(sy, inv_k, -dqy))
            + fabsf(fmaf(sz, inv_k, -dqz));
    }

    // ---- Phase 6: deterministic block reduction ----
    float* red = reinterpret_cast<float*>(sval + 2 * THREADS * KP1);
    red[tid] = acc;
    __syncthreads();
#pragma unroll
    for (int s = THREADS / 2; s > 0; s >>= 1) {
        if (tid < s) red[tid] += red[tid + s];
        __syncthreads();
    }
    if (tid == 0) g_partials[blockIdx.x] = red[0];
}

__global__ void final_reduce_kernel(float* __restrict__ out) {
    __shared__ float s[NBLOCKS];
    const int t = threadIdx.x;
    s[t] = g_partials[t];
    __syncthreads();
#pragma unroll
    for (int st = NBLOCKS / 2; st > 0; st >>= 1) {
        if (t < st) s[t] += s[t + st];
        __syncthreads();
    }
    if (t == 0) out[0] = s[0] * (1.0f / (float)(B_ * N_ * 3));
}

extern "C" void kernel_launch(void* const* d_in, const int* in_sizes, int n_in,
                              void* d_out, int out_size) {
    const float* p1 = (const float*)d_in[0];
    const float* p2 = (const float*)d_in[1];
    (void)in_sizes; (void)n_in; (void)out_size;

    cudaFuncSetAttribute(knn_lap_loss_kernel,
                         cudaFuncAttributeMaxDynamicSharedMemorySize, SMEM_BYTES);
    knn_lap_loss_kernel<<<NBLOCKS, THREADS, SMEM_BYTES>>>(p1, p2);
    final_reduce_kernel<<<1, NBLOCKS>>>((float*)d_out);
}